// round 1
// baseline (speedup 1.0000x reference)
#include <cuda_runtime.h>

// ---------------------------------------------------------------------------
// RgbNet fused kernel: per-ray 5-sample hash-grid encoding + 4-layer MLP.
//
// Reference computes grid encoding for all 300 samples/ray but only reads 5
// of them (indices_first + {-2..2}). We compute exactly those 5.
//
// Layout: 1 warp per ray. Lanes 0..29 -> (sample s = lane/6, level l = lane%6),
// each lane does the 8-corner trilinear gather for its (s,l) and writes 4
// feature floats to shared. Then the warp cooperatively runs the MLP with
// weights staged (transposed) in shared memory.
// ---------------------------------------------------------------------------

namespace {
constexpr int NRAYS   = 16384;
constexpr int NSAMP   = 300;
constexpr unsigned HSIZE = 1u << 19;          // 524288
constexpr unsigned HMASK = HSIZE - 1u;
constexpr int WARPS   = 16;                    // rays per block
constexpr int THREADS = WARPS * 32;

// shared layout (floats)
constexpr int OFF_W1T = 0;                     // [120][64]
constexpr int OFF_W2T = OFF_W1T + 120 * 64;    // [64][64]
constexpr int OFF_W3T = OFF_W2T + 64 * 64;     // [64][64]
constexpr int OFF_W4  = OFF_W3T + 64 * 64;     // [3][64] row-major
constexpr int OFF_B1  = OFF_W4 + 192;
constexpr int OFF_B2  = OFF_B1 + 64;
constexpr int OFF_B3  = OFF_B2 + 64;
constexpr int OFF_B4  = OFF_B3 + 64;           // 4 (padded)
constexpr int OFF_WBUF= OFF_B4 + 4;            // per-warp: feat[120] + h[64] = 184
constexpr int WBUF_STRIDE = 184;               // 736 B, 16B-aligned
constexpr int SH_FLOATS = OFF_WBUF + WARPS * WBUF_STRIDE;
}

__global__ __launch_bounds__(THREADS, 2)
void rgbnet_fused(const float* __restrict__ x,        // [N,4]
                  const int*   __restrict__ ifirst,   // [N]
                  const float* __restrict__ emb,      // [6, 2^19, 4]
                  const float* __restrict__ W1, const float* __restrict__ b1,
                  const float* __restrict__ W2, const float* __restrict__ b2,
                  const float* __restrict__ W3, const float* __restrict__ b3,
                  const float* __restrict__ W4, const float* __restrict__ b4,
                  float* __restrict__ out)             // [N,3]
{
    extern __shared__ float sh[];
    float* W1t = sh + OFF_W1T;
    float* W2t = sh + OFF_W2T;
    float* W3t = sh + OFF_W3T;
    float* W4s = sh + OFF_W4;
    float* b1s = sh + OFF_B1;
    float* b2s = sh + OFF_B2;
    float* b3s = sh + OFF_B3;
    float* b4s = sh + OFF_B4;

    const int tid = threadIdx.x;

    // ---- stage weights (transposed so the MLP reads are conflict-free) ----
    for (int i = tid; i < 64 * 120; i += THREADS) {
        int o = i / 120, k = i - o * 120;
        W1t[k * 64 + o] = W1[i];
    }
    for (int i = tid; i < 64 * 64; i += THREADS) {
        int o = i >> 6, k = i & 63;
        W2t[k * 64 + o] = W2[i];
        W3t[k * 64 + o] = W3[i];
    }
    if (tid < 192) W4s[tid] = W4[tid];
    if (tid < 64) { b1s[tid] = b1[tid]; b2s[tid] = b2[tid]; b3s[tid] = b3[tid]; }
    if (tid < 4)  b4s[tid] = (tid < 3) ? b4[tid] : 0.0f;
    __syncthreads();

    const int warp = tid >> 5;
    const int lane = tid & 31;
    const int ray  = blockIdx.x * WARPS + warp;
    if (ray >= NRAYS) return;

    float* feat = sh + OFF_WBUF + warp * WBUF_STRIDE;   // [120]
    float* hbuf = feat + 120;                           // [64]

    const float4 xr   = *reinterpret_cast<const float4*>(x + (size_t)ray * 4);
    const int    idxf = ifirst[ray];

    // ---------------- hash-grid encoding: 5 samples x 6 levels ----------------
    if (lane < 30) {
        const int s = lane / 6;          // 0..4  (sample offset index)
        const int l = lane - s * 6;      // 0..5  (level)

        int sc = idxf + s - 2;
        sc = sc < 0 ? 0 : (sc > NSAMP - 1 ? NSAMP - 1 : sc);
        const float t   = (float)sc * (1.0f / 299.0f);
        const float omt = 1.0f - t;
        const float px = xr.x * omt + xr.z * t;
        const float py = xr.y * omt + xr.w * t;
        const float pz = t;

        const int   R   = 4 << l;
        const float fR  = (float)R;
        const float fx = px * fR, fy = py * fR, fz = pz * fR;
        const float flx = floorf(fx), fly = floorf(fy), flz = floorf(fz);
        const int ix = (int)flx, iy = (int)fly, iz = (int)flz;
        const float wx = fx - flx, wy = fy - fly, wz = fz - flz;
        const int Rp1 = R + 1;

        const float4* __restrict__ tab =
            reinterpret_cast<const float4*>(emb) + (size_t)l * HSIZE;

        float ax = 0.f, ay = 0.f, az = 0.f, aw = 0.f;
        #pragma unroll
        for (int c = 0; c < 8; c++) {
            const int bx = (c >> 2) & 1, by = (c >> 1) & 1, bz = c & 1;
            int cx = ix + bx; cx = cx > R ? R : cx;
            int cy = iy + by; cy = cy > R ? R : cy;
            int cz = iz + bz; cz = cz > R ? R : cz;
            const unsigned id_dense =
                (unsigned)(cx + cy * Rp1 + cz * Rp1 * Rp1);
            const unsigned id_hash =
                ((unsigned)cx ^ ((unsigned)cy * 2654435761u)
                             ^ ((unsigned)cz * 805459861u)) & HMASK;
            const unsigned idx = (l == 5) ? id_hash : id_dense;
            const float4 e = __ldg(tab + idx);
            const float wgt = (bx ? wx : 1.0f - wx)
                            * (by ? wy : 1.0f - wy)
                            * (bz ? wz : 1.0f - wz);
            ax = fmaf(wgt, e.x, ax);
            ay = fmaf(wgt, e.y, ay);
            az = fmaf(wgt, e.z, az);
            aw = fmaf(wgt, e.w, aw);
        }
        float* f = feat + s * 24 + l * 4;
        f[0] = ax; f[1] = ay; f[2] = az; f[3] = aw;
    }
    __syncwarp();

    // ---------------- MLP: each lane computes outputs 2*lane, 2*lane+1 --------
    const int o2 = lane * 2;

    // layer 1: 120 -> 64, relu
    float a0 = b1s[o2], a1 = b1s[o2 + 1];
    #pragma unroll
    for (int k = 0; k < 120; k += 4) {
        const float4 f4 = *reinterpret_cast<const float4*>(feat + k);
        float2 w;
        w = *reinterpret_cast<const float2*>(W1t + (k + 0) * 64 + o2);
        a0 = fmaf(f4.x, w.x, a0); a1 = fmaf(f4.x, w.y, a1);
        w = *reinterpret_cast<const float2*>(W1t + (k + 1) * 64 + o2);
        a0 = fmaf(f4.y, w.x, a0); a1 = fmaf(f4.y, w.y, a1);
        w = *reinterpret_cast<const float2*>(W1t + (k + 2) * 64 + o2);
        a0 = fmaf(f4.z, w.x, a0); a1 = fmaf(f4.z, w.y, a1);
        w = *reinterpret_cast<const float2*>(W1t + (k + 3) * 64 + o2);
        a0 = fmaf(f4.w, w.x, a0); a1 = fmaf(f4.w, w.y, a1);
    }
    a0 = fmaxf(a0, 0.0f); a1 = fmaxf(a1, 0.0f);
    reinterpret_cast<float2*>(hbuf)[lane] = make_float2(a0, a1);
    __syncwarp();

    // layer 2: 64 -> 64, relu
    a0 = b2s[o2]; a1 = b2s[o2 + 1];
    #pragma unroll
    for (int k = 0; k < 64; k += 4) {
        const float4 f4 = *reinterpret_cast<const float4*>(hbuf + k);
        float2 w;
        w = *reinterpret_cast<const float2*>(W2t + (k + 0) * 64 + o2);
        a0 = fmaf(f4.x, w.x, a0); a1 = fmaf(f4.x, w.y, a1);
        w = *reinterpret_cast<const float2*>(W2t + (k + 1) * 64 + o2);
        a0 = fmaf(f4.y, w.x, a0); a1 = fmaf(f4.y, w.y, a1);
        w = *reinterpret_cast<const float2*>(W2t + (k + 2) * 64 + o2);
        a0 = fmaf(f4.z, w.x, a0); a1 = fmaf(f4.z, w.y, a1);
        w = *reinterpret_cast<const float2*>(W2t + (k + 3) * 64 + o2);
        a0 = fmaf(f4.w, w.x, a0); a1 = fmaf(f4.w, w.y, a1);
    }
    a0 = fmaxf(a0, 0.0f); a1 = fmaxf(a1, 0.0f);
    __syncwarp();                               // all lanes done reading hbuf
    reinterpret_cast<float2*>(hbuf)[lane] = make_float2(a0, a1);
    __syncwarp();

    // layer 3: 64 -> 64, relu
    a0 = b3s[o2]; a1 = b3s[o2 + 1];
    #pragma unroll
    for (int k = 0; k < 64; k += 4) {
        const float4 f4 = *reinterpret_cast<const float4*>(hbuf + k);
        float2 w;
        w = *reinterpret_cast<const float2*>(W3t + (k + 0) * 64 + o2);
        a0 = fmaf(f4.x, w.x, a0); a1 = fmaf(f4.x, w.y, a1);
        w = *reinterpret_cast<const float2*>(W3t + (k + 1) * 64 + o2);
        a0 = fmaf(f4.y, w.x, a0); a1 = fmaf(f4.y, w.y, a1);
        w = *reinterpret_cast<const float2*>(W3t + (k + 2) * 64 + o2);
        a0 = fmaf(f4.z, w.x, a0); a1 = fmaf(f4.z, w.y, a1);
        w = *reinterpret_cast<const float2*>(W3t + (k + 3) * 64 + o2);
        a0 = fmaf(f4.w, w.x, a0); a1 = fmaf(f4.w, w.y, a1);
    }
    a0 = fmaxf(a0, 0.0f); a1 = fmaxf(a1, 0.0f);
    __syncwarp();
    reinterpret_cast<float2*>(hbuf)[lane] = make_float2(a0, a1);
    __syncwarp();

    // layer 4: 64 -> 3
    if (lane < 3) {
        float acc = b4s[lane];
        #pragma unroll
        for (int k = 0; k < 64; k++)
            acc = fmaf(hbuf[k], W4s[lane * 64 + k], acc);
        out[(size_t)ray * 3 + lane] = acc;
    }
}

extern "C" void kernel_launch(void* const* d_in, const int* in_sizes, int n_in,
                              void* d_out, int out_size) {
    const float* x    = (const float*)d_in[0];
    const int*   idxf = (const int*)  d_in[1];
    const float* emb  = (const float*)d_in[2];
    const float* W1   = (const float*)d_in[3];
    const float* b1   = (const float*)d_in[4];
    const float* W2   = (const float*)d_in[5];
    const float* b2   = (const float*)d_in[6];
    const float* W3   = (const float*)d_in[7];
    const float* b3   = (const float*)d_in[8];
    const float* W4   = (const float*)d_in[9];
    const float* b4   = (const float*)d_in[10];
    float* out = (float*)d_out;

    const size_t shbytes = (size_t)SH_FLOATS * sizeof(float);   // ~76.8 KB
    cudaFuncSetAttribute(rgbnet_fused,
                         cudaFuncAttributeMaxDynamicSharedMemorySize,
                         (int)shbytes);

    rgbnet_fused<<<NRAYS / WARPS, THREADS, shbytes>>>(
        x, idxf, emb, W1, b1, W2, b2, W3, b3, W4, b4, out);
}

// round 2
// speedup vs baseline: 2.0094x; 2.0094x over previous
#include <cuda_runtime.h>

// ---------------------------------------------------------------------------
// RgbNet fused: 5-sample hash-grid encoding + 4-layer MLP, restructured.
//
// R2 changes vs R1:
//  * Weights pre-transposed into __device__ global by a tiny kernel; main
//    blocks stage them conflict-free (coalesced LDG -> consecutive STS).
//  * 64 rays per block; MLP warp = (16 outputs) x (32 rays), lane = ray.
//    Weight reads are broadcast LDS.128 (1 wavefront), activations live in
//    transposed shared [k][ray] (conflict-free).
//  * fp32x2 packed FMA (fma.rn.f32x2) for 2 output neurons per instruction.
// ---------------------------------------------------------------------------

namespace {
constexpr int NRAYS   = 16384;
constexpr int NSAMP   = 300;
constexpr unsigned HSIZE = 1u << 19;
constexpr unsigned HMASK = HSIZE - 1u;
constexpr int RPB     = 64;                 // rays per block
constexpr int THREADS = 256;
constexpr int NBLK    = NRAYS / RPB;        // 256

// shared layout (float offsets)
constexpr int OFF_W1T  = 0;                       // [120][64]
constexpr int OFF_W2T  = OFF_W1T + 120 * 64;      // [64][64]
constexpr int OFF_W3T  = OFF_W2T + 64 * 64;       // [64][64]
constexpr int OFF_W4   = OFF_W3T + 64 * 64;       // [3][64]
constexpr int OFF_B1   = OFF_W4 + 192;
constexpr int OFF_B2   = OFF_B1 + 64;
constexpr int OFF_B3   = OFF_B2 + 64;
constexpr int OFF_B4   = OFF_B3 + 64;             // 4 (padded)
constexpr int OFF_FEAT = OFF_B4 + 4;              // [120][64], swizzled cols
constexpr int OFF_H    = OFF_FEAT + 120 * 64;     // [64][64]; aliases xs/ifs
constexpr int SH_FLOATS = OFF_H + 64 * 64;        // 28036 floats = 112144 B
constexpr int WSTAGE   = 120 * 64 + 64 * 64 + 64 * 64;  // 15872
}

__device__ float g_Wt[WSTAGE];   // [W1t | W2t | W3t], each [k][o]

// ---- tiny pre-transpose kernel (runs once per replay; negligible) --------
__global__ void transpose_weights(const float* __restrict__ W1,
                                  const float* __restrict__ W2,
                                  const float* __restrict__ W3) {
    int i = blockIdx.x * blockDim.x + threadIdx.x;
    if (i < 7680) {
        int k = i >> 6, o = i & 63;
        g_Wt[i] = W1[o * 120 + k];
    } else if (i < 11776) {
        int j = i - 7680; int k = j >> 6, o = j & 63;
        g_Wt[i] = W2[o * 64 + k];
    } else if (i < WSTAGE) {
        int j = i - 11776; int k = j >> 6, o = j & 63;
        g_Wt[i] = W3[o * 64 + k];
    }
}

// ---- fp32x2 helpers -------------------------------------------------------
__device__ __forceinline__ unsigned long long pack2(float v) {
    unsigned long long r;
    asm("mov.b64 %0, {%1, %1};" : "=l"(r) : "f"(v));
    return r;
}
__device__ __forceinline__ float2 unpack2(unsigned long long v) {
    float2 r;
    asm("mov.b64 {%0, %1}, %2;" : "=f"(r.x), "=f"(r.y) : "l"(v));
    return r;
}
#define FMA2(acc, a, b) \
    asm("fma.rn.f32x2 %0, %1, %2, %0;" : "+l"(acc) : "l"(a), "l"(b))

// One MLP layer: this warp computes outputs [obase, obase+16) for 32 rays
// (lane = ray). fin is [KDIM][64] (optionally swizzled), fout is [64][64].
template <int KDIM, bool SWZ>
__device__ __forceinline__ void mlp_layer(const float* __restrict__ Wt,
                                          const float* __restrict__ bias,
                                          const float* __restrict__ fin,
                                          float*       __restrict__ fout,
                                          int obase, int ridx) {
    unsigned long long acc[8];
    const unsigned long long* bp =
        reinterpret_cast<const unsigned long long*>(bias + obase);
    #pragma unroll
    for (int p = 0; p < 8; p++) acc[p] = bp[p];

    #pragma unroll 4
    for (int k = 0; k < KDIM; k++) {
        const int col = SWZ ? (ridx ^ (k & 31)) : ridx;
        const float f = fin[k * 64 + col];
        const unsigned long long ff = pack2(f);
        const ulonglong2* wp =
            reinterpret_cast<const ulonglong2*>(Wt + k * 64 + obase);
        const ulonglong2 w0 = wp[0], w1 = wp[1], w2 = wp[2], w3 = wp[3];
        FMA2(acc[0], ff, w0.x); FMA2(acc[1], ff, w0.y);
        FMA2(acc[2], ff, w1.x); FMA2(acc[3], ff, w1.y);
        FMA2(acc[4], ff, w2.x); FMA2(acc[5], ff, w2.y);
        FMA2(acc[6], ff, w3.x); FMA2(acc[7], ff, w3.y);
    }
    #pragma unroll
    for (int p = 0; p < 8; p++) {
        const float2 a = unpack2(acc[p]);
        fout[(obase + 2 * p)     * 64 + ridx] = fmaxf(a.x, 0.0f);
        fout[(obase + 2 * p + 1) * 64 + ridx] = fmaxf(a.y, 0.0f);
    }
}

__global__ __launch_bounds__(THREADS, 2)
void rgbnet_main(const float* __restrict__ x,        // [N,4]
                 const int*   __restrict__ ifirst,   // [N]
                 const float* __restrict__ emb,      // [6, 2^19, 4]
                 const float* __restrict__ W4,
                 const float* __restrict__ b1, const float* __restrict__ b2,
                 const float* __restrict__ b3, const float* __restrict__ b4,
                 float* __restrict__ out)             // [N,3]
{
    extern __shared__ float sh[];
    const int tid = threadIdx.x;

    // ---- stage pre-transposed weights: coalesced LDG -> consecutive STS ---
    for (int i = tid; i < WSTAGE; i += THREADS) sh[i] = g_Wt[i];
    if (tid < 192) sh[OFF_W4 + tid] = W4[tid];
    if (tid < 64) {
        sh[OFF_B1 + tid] = b1[tid];
        sh[OFF_B2 + tid] = b2[tid];
        sh[OFF_B3 + tid] = b3[tid];
    }
    if (tid < 4) sh[OFF_B4 + tid] = (tid < 3) ? b4[tid] : 0.0f;

    // ---- stage this block's rays (xs/ifs alias the h buffer) --------------
    const int ray0 = blockIdx.x * RPB;
    float4* xs4 = reinterpret_cast<float4*>(sh + OFF_H);
    int*    ifs = reinterpret_cast<int*>(sh + OFF_H + RPB * 4);
    if (tid < RPB) {
        xs4[tid] = reinterpret_cast<const float4*>(x)[ray0 + tid];
        ifs[tid] = ifirst[ray0 + tid];
    }
    __syncthreads();

    float* feat = sh + OFF_FEAT;

    // ---- encoding: 64 rays x 30 (sample,level) tasks, ray-fastest mapping -
    // (warps are uniform in (s,l); feat writes are swizzle-conflict-free)
    for (int t = tid; t < RPB * 30; t += THREADS) {
        const int r     = t & 63;
        const int combo = t >> 6;            // 0..29, = s*6 + l
        const int s = combo / 6;
        const int l = combo - s * 6;

        const float4 xr = xs4[r];
        int sc = ifs[r] + s - 2;
        sc = sc < 0 ? 0 : (sc > NSAMP - 1 ? NSAMP - 1 : sc);
        const float tt  = (float)sc * (1.0f / 299.0f);
        const float omt = 1.0f - tt;
        const float px = xr.x * omt + xr.z * tt;
        const float py = xr.y * omt + xr.w * tt;
        const float pz = tt;

        const int   R  = 4 << l;
        const float fR = (float)R;
        const float fx = px * fR, fy = py * fR, fz = pz * fR;
        const float flx = floorf(fx), fly = floorf(fy), flz = floorf(fz);
        const int ix = (int)flx, iy = (int)fly, iz = (int)flz;
        const float wx = fx - flx, wy = fy - fly, wz = fz - flz;
        const int Rp1 = R + 1;

        const float4* __restrict__ tab =
            reinterpret_cast<const float4*>(emb) + (size_t)l * HSIZE;

        float ax = 0.f, ay = 0.f, az = 0.f, aw = 0.f;
        #pragma unroll
        for (int c = 0; c < 8; c++) {
            const int bx = (c >> 2) & 1, by = (c >> 1) & 1, bz = c & 1;
            int cx = ix + bx; cx = cx > R ? R : cx;
            int cy = iy + by; cy = cy > R ? R : cy;
            int cz = iz + bz; cz = cz > R ? R : cz;
            const unsigned id_dense =
                (unsigned)(cx + cy * Rp1 + cz * Rp1 * Rp1);
            const unsigned id_hash =
                ((unsigned)cx ^ ((unsigned)cy * 2654435761u)
                             ^ ((unsigned)cz * 805459861u)) & HMASK;
            const unsigned idx = (l == 5) ? id_hash : id_dense;
            const float4 e = __ldg(tab + idx);
            const float wgt = (bx ? wx : 1.0f - wx)
                            * (by ? wy : 1.0f - wy)
                            * (bz ? wz : 1.0f - wz);
            ax = fmaf(wgt, e.x, ax);
            ay = fmaf(wgt, e.y, ay);
            az = fmaf(wgt, e.z, az);
            aw = fmaf(wgt, e.w, aw);
        }
        // feature indices k = combo*4 + j; swizzled column for bank-freedom
        const int kb = combo * 4;
        feat[(kb + 0) * 64 + (r ^ ((kb + 0) & 31))] = ax;
        feat[(kb + 1) * 64 + (r ^ ((kb + 1) & 31))] = ay;
        feat[(kb + 2) * 64 + (r ^ ((kb + 2) & 31))] = az;
        feat[(kb + 3) * 64 + (r ^ ((kb + 3) & 31))] = aw;
    }
    __syncthreads();

    // ---- MLP: warp q handles outputs [(q&3)*16, +16) for rays rbase..+31 --
    const int lane  = tid & 31;
    const int warp  = tid >> 5;
    const int obase = (warp & 3) * 16;
    const int ridx  = (warp >> 2) * 32 + lane;    // ray within block
    float* hbuf = sh + OFF_H;

    mlp_layer<120, true >(sh + OFF_W1T, sh + OFF_B1, feat, hbuf, obase, ridx);
    __syncthreads();
    mlp_layer<64,  false>(sh + OFF_W2T, sh + OFF_B2, hbuf, feat, obase, ridx);
    __syncthreads();
    mlp_layer<64,  false>(sh + OFF_W3T, sh + OFF_B3, feat, hbuf, obase, ridx);
    __syncthreads();

    // ---- layer 4: 64 -> 3, one thread per ray ------------------------------
    if (tid < RPB) {
        const float* W4s = sh + OFF_W4;
        float a0 = sh[OFF_B4 + 0], a1 = sh[OFF_B4 + 1], a2 = sh[OFF_B4 + 2];
        #pragma unroll 8
        for (int k = 0; k < 64; k++) {
            const float hv = hbuf[k * 64 + tid];
            a0 = fmaf(hv, W4s[k],        a0);
            a1 = fmaf(hv, W4s[64 + k],   a1);
            a2 = fmaf(hv, W4s[128 + k],  a2);
        }
        float* o = out + (size_t)(ray0 + tid) * 3;
        o[0] = a0; o[1] = a1; o[2] = a2;
    }
}

extern "C" void kernel_launch(void* const* d_in, const int* in_sizes, int n_in,
                              void* d_out, int out_size) {
    const float* x    = (const float*)d_in[0];
    const int*   idxf = (const int*)  d_in[1];
    const float* emb  = (const float*)d_in[2];
    const float* W1   = (const float*)d_in[3];
    const float* b1   = (const float*)d_in[4];
    const float* W2   = (const float*)d_in[5];
    const float* b2   = (const float*)d_in[6];
    const float* W3   = (const float*)d_in[7];
    const float* b3   = (const float*)d_in[8];
    const float* W4   = (const float*)d_in[9];
    const float* b4   = (const float*)d_in[10];
    float* out = (float*)d_out;

    transpose_weights<<<(WSTAGE + 255) / 256, 256>>>(W1, W2, W3);

    const size_t shbytes = (size_t)SH_FLOATS * sizeof(float);  // 112144 B
    cudaFuncSetAttribute(rgbnet_main,
                         cudaFuncAttributeMaxDynamicSharedMemorySize,
                         (int)shbytes);
    rgbnet_main<<<NBLK, THREADS, shbytes>>>(
        x, idxf, emb, W4, b1, b2, b3, b4, out);
}